// round 10
// baseline (speedup 1.0000x reference)
#include <cuda_runtime.h>
#include <cuda_bf16.h>
#include <stdint.h>

#define BB 4
#define NN 2048
#define MM 8192
#define DD 128
#define SS 1024     // NUM_SEGMENTS
#define HB 8        // source chunks per batch, 1024 rows each
#define HBT 2       // target chunks per batch, 1024 rows each
#define NSRC_BLKS (BB * HB)            // 32
#define NTGT_BLKS (BB * HBT)           // 8
#define NBLK (NSRC_BLKS + NTGT_BLKS)   // 40
#define STAGE_CAP 96                   // max staged rows per segment (P(exceed) ~ 0)

// ---------------- scratch (static __device__, no allocation) ----------------
// meta[(b*SS+s)*CH + j] = {cnt, local_off} of segment s within chunk j
__device__ int2 g_meta_s[BB * SS * HB];
__device__ int2 g_meta_t[BB * SS * HBT];
__device__ int  g_rows_s[BB * MM];   // rows grouped by segment WITHIN each chunk
__device__ int  g_rows_t[BB * NN];

// ---------------- 1) block-local sort: hist + local scan + local scatter ----------
__global__ __launch_bounds__(256) void k_sort(const int* __restrict__ idx_src,
                                              const int* __restrict__ idx_tgt) {
    __shared__ int sh[SS];
    __shared__ int wsum[8];
    const int t = threadIdx.x;
    const int lane = t & 31;
    const int w = t >> 5;

    const int* in;
    int*  rows;
    int2* meta;
    int   ch_stride;
    int   chunk;
    if (blockIdx.x < NSRC_BLKS) {
        int b = blockIdx.x >> 3, i = blockIdx.x & 7;
        in   = idx_src + b * MM + i * 1024;
        rows = g_rows_s + b * MM + i * 1024;
        meta = g_meta_s + (b * SS) * HB + i;
        ch_stride = HB; chunk = i;
    } else {
        int u = blockIdx.x - NSRC_BLKS;
        int b = u >> 1, i = u & 1;
        in   = idx_tgt + b * NN + i * 1024;
        rows = g_rows_t + b * NN + i * 1024;
        meta = g_meta_t + (b * SS) * HBT + i;
        ch_stride = HBT; chunk = i;
    }

    // hist
    ((int4*)sh)[t] = make_int4(0, 0, 0, 0);
    __syncthreads();
    const int4 a = ((const int4*)in)[t];
    atomicAdd(&sh[a.x], 1); atomicAdd(&sh[a.y], 1);
    atomicAdd(&sh[a.z], 1); atomicAdd(&sh[a.w], 1);
    __syncthreads();

    // local exclusive scan over 1024 bins (thread owns bins 4t..4t+3)
    int4 tot = ((int4*)sh)[t];
    int l0 = tot.x, l1 = l0 + tot.y, l2 = l1 + tot.z, l3 = l2 + tot.w;
    int inc = l3;
    #pragma unroll
    for (int d = 1; d < 32; d <<= 1) {
        int up = __shfl_up_sync(0xffffffffu, inc, d);
        if (lane >= d) inc += up;
    }
    if (lane == 31) wsum[w] = inc;
    __syncthreads();
    if (w == 0) {
        int v = (lane < 8) ? wsum[lane] : 0;
        #pragma unroll
        for (int d = 1; d < 8; d <<= 1) {
            int up = __shfl_up_sync(0xffffffffu, v, d);
            if (lane >= d) v += up;
        }
        if (lane < 8) wsum[lane] = v;
    }
    __syncthreads();
    int excl = inc - l3 + (w > 0 ? wsum[w - 1] : 0);
    int o0 = excl, o1 = excl + l0, o2 = excl + l1, o3 = excl + l2;

    // publish per-chunk meta {cnt, local_off}
    int s = 4 * t;
    meta[(s + 0) * ch_stride] = make_int2(tot.x, o0);
    meta[(s + 1) * ch_stride] = make_int2(tot.y, o1);
    meta[(s + 2) * ch_stride] = make_int2(tot.z, o2);
    meta[(s + 3) * ch_stride] = make_int2(tot.w, o3);

    // cursors
    sh[s + 0] = o0; sh[s + 1] = o1; sh[s + 2] = o2; sh[s + 3] = o3;
    __syncthreads();

    // local scatter; batch-relative row id
    int m = chunk * 1024 + 4 * t;
    int q;
    q = atomicAdd(&sh[a.x], 1); rows[q] = m + 0;
    q = atomicAdd(&sh[a.y], 1); rows[q] = m + 1;
    q = atomicAdd(&sh[a.z], 1); rows[q] = m + 2;
    q = atomicAdd(&sh[a.w], 1); rows[q] = m + 3;
}

// ---------------- 2) segsum + write: FOUR warps per segment (D split in quarters) ----
__global__ __launch_bounds__(256) void k_segsum_write(const float* __restrict__ src,
                                                      float* __restrict__ out) {
    __shared__ int stage[8][STAGE_CAP];
    int gw   = (blockIdx.x * blockDim.x + threadIdx.x) >> 5;   // 0..BB*SS*4-1
    int lane = threadIdx.x & 31;
    int w    = (threadIdx.x >> 5) & 7;
    if (gw >= BB * SS * 4) return;
    int seg = gw >> 2;          // segment id
    int dq  = gw & 3;           // D-quarter: floats [dq*32, dq*32+32)
    int b   = seg >> 10;

    // lane-parallel meta load: 16 src ints + 4 tgt ints
    const int* ms_raw = (const int*)(g_meta_s + (size_t)seg * HB);
    const int* mt_raw = (const int*)(g_meta_t + (size_t)seg * HBT);
    int mv = 0;
    if (lane < 16)      mv = ms_raw[lane];
    else if (lane < 20) mv = mt_raw[lane - 16];

    int tc0 = __shfl_sync(0xffffffffu, mv, 16);
    int to0 = __shfl_sync(0xffffffffu, mv, 17);
    int tc1 = __shfl_sync(0xffffffffu, mv, 18);
    int to1 = __shfl_sync(0xffffffffu, mv, 19);
    if (tc0 + tc1 == 0) return;

    int cj[HB], oj[HB], pj[HB];
    int cnt = 0;
    #pragma unroll
    for (int j = 0; j < HB; j++) {
        cj[j] = __shfl_sync(0xffffffffu, mv, 2 * j);
        oj[j] = __shfl_sync(0xffffffffu, mv, 2 * j + 1);
        pj[j] = cnt;
        cnt += cj[j];
    }

    // this warp reads a 128B quarter of each row: scalar float per lane
    const float* base = src + (size_t)b * MM * DD + dq * 32 + lane;
    float a0 = 0.f, a1 = 0.f, a2 = 0.f, a3 = 0.f;

    if (cnt <= STAGE_CAP) {
        if (lane < HB) {
            int c = cj[lane], o = oj[lane], p = pj[lane];
            const int* rp = g_rows_s + b * MM + lane * 1024 + o;
            for (int r = 0; r < c; r++) stage[w][p + r] = rp[r];
        }
        __syncwarp();

        const int* mlist = stage[w];
        int r = 0;
        for (; r + 8 <= cnt; r += 8) {
            float v0 = base[(size_t)mlist[r]     * DD];
            float v1 = base[(size_t)mlist[r + 1] * DD];
            float v2 = base[(size_t)mlist[r + 2] * DD];
            float v3 = base[(size_t)mlist[r + 3] * DD];
            float v4 = base[(size_t)mlist[r + 4] * DD];
            float v5 = base[(size_t)mlist[r + 5] * DD];
            float v6 = base[(size_t)mlist[r + 6] * DD];
            float v7 = base[(size_t)mlist[r + 7] * DD];
            a0 += v0 + v4; a1 += v1 + v5; a2 += v2 + v6; a3 += v3 + v7;
        }
        for (; r + 4 <= cnt; r += 4) {
            float v0 = base[(size_t)mlist[r]     * DD];
            float v1 = base[(size_t)mlist[r + 1] * DD];
            float v2 = base[(size_t)mlist[r + 2] * DD];
            float v3 = base[(size_t)mlist[r + 3] * DD];
            a0 += v0; a1 += v1; a2 += v2; a3 += v3;
        }
        for (; r < cnt; r++) {
            a0 += base[(size_t)mlist[r] * DD];
        }
    } else {
        // overflow fallback (practically never taken)
        #pragma unroll
        for (int j = 0; j < HB; j++) {
            const int* rp = g_rows_s + b * MM + j * 1024 + oj[j];
            for (int r = 0; r < cj[j]; r++) {
                a0 += base[(size_t)rp[r] * DD];
            }
        }
    }

    float res = (a0 + a1 + a2 + a3) / ((float)cnt + 1e-10f);

    // write this quarter of every target row
    float* outb = out + (size_t)b * NN * DD + dq * 32 + lane;
    const int* tp0 = g_rows_t + b * NN + to0;
    for (int r = 0; r < tc0; r++) {
        outb[(size_t)tp0[r] * DD] = res;
    }
    const int* tp1 = g_rows_t + b * NN + 1024 + to1;
    for (int r = 0; r < tc1; r++) {
        outb[(size_t)tp1[r] * DD] = res;
    }
}

// ---------------- launch ----------------
extern "C" void kernel_launch(void* const* d_in, const int* in_sizes, int n_in,
                              void* d_out, int out_size) {
    const int*   idx_tgt = (const int*)d_in[0];
    const int*   idx_src = (const int*)d_in[1];
    const float* src     = (const float*)d_in[2];
    float*       out     = (float*)d_out;

    k_sort        <<<NBLK, 256>>>(idx_src, idx_tgt);
    k_segsum_write<<<(BB * SS * 4 * 32 + 255) / 256, 256>>>(src, out);
}

// round 11
// speedup vs baseline: 1.2225x; 1.2225x over previous
#include <cuda_runtime.h>
#include <cuda_bf16.h>
#include <stdint.h>

#define BB 4
#define NN 2048
#define MM 8192
#define DD 128
#define SS 1024     // NUM_SEGMENTS
#define HB 8        // source chunks per batch, 1024 rows each
#define HBT 2       // target chunks per batch, 1024 rows each
#define NSRC_BLKS (BB * HB)            // 32
#define NTGT_BLKS (BB * HBT)           // 8
#define NBLK (NSRC_BLKS + NTGT_BLKS)   // 40
#define STAGE_CAP 96                   // max staged rows per segment (P(exceed) ~ 0)

// ---------------- scratch (static __device__, no allocation) ----------------
__device__ int2 g_meta_s[BB * SS * HB];
__device__ int2 g_meta_t[BB * SS * HBT];
__device__ int  g_rows_s[BB * MM];   // rows grouped by segment WITHIN each chunk
__device__ int  g_rows_t[BB * NN];

// ---------------- 1) block-local sort: hist + local scan + local scatter ----------
__global__ __launch_bounds__(256) void k_sort(const int* __restrict__ idx_src,
                                              const int* __restrict__ idx_tgt) {
    __shared__ int sh[SS];
    __shared__ int wsum[8];
    const int t = threadIdx.x;
    const int lane = t & 31;
    const int w = t >> 5;

    const int* in;
    int*  rows;
    int2* meta;
    int   ch_stride;
    int   chunk;
    if (blockIdx.x < NSRC_BLKS) {
        int b = blockIdx.x >> 3, i = blockIdx.x & 7;
        in   = idx_src + b * MM + i * 1024;
        rows = g_rows_s + b * MM + i * 1024;
        meta = g_meta_s + (b * SS) * HB + i;
        ch_stride = HB; chunk = i;
    } else {
        int u = blockIdx.x - NSRC_BLKS;
        int b = u >> 1, i = u & 1;
        in   = idx_tgt + b * NN + i * 1024;
        rows = g_rows_t + b * NN + i * 1024;
        meta = g_meta_t + (b * SS) * HBT + i;
        ch_stride = HBT; chunk = i;
    }

    // hist
    ((int4*)sh)[t] = make_int4(0, 0, 0, 0);
    __syncthreads();
    const int4 a = ((const int4*)in)[t];
    atomicAdd(&sh[a.x], 1); atomicAdd(&sh[a.y], 1);
    atomicAdd(&sh[a.z], 1); atomicAdd(&sh[a.w], 1);
    __syncthreads();

    // local exclusive scan over 1024 bins (thread owns bins 4t..4t+3)
    int4 tot = ((int4*)sh)[t];
    int l0 = tot.x, l1 = l0 + tot.y, l2 = l1 + tot.z, l3 = l2 + tot.w;
    int inc = l3;
    #pragma unroll
    for (int d = 1; d < 32; d <<= 1) {
        int up = __shfl_up_sync(0xffffffffu, inc, d);
        if (lane >= d) inc += up;
    }
    if (lane == 31) wsum[w] = inc;
    __syncthreads();
    if (w == 0) {
        int v = (lane < 8) ? wsum[lane] : 0;
        #pragma unroll
        for (int d = 1; d < 8; d <<= 1) {
            int up = __shfl_up_sync(0xffffffffu, v, d);
            if (lane >= d) v += up;
        }
        if (lane < 8) wsum[lane] = v;
    }
    __syncthreads();
    int excl = inc - l3 + (w > 0 ? wsum[w - 1] : 0);
    int o0 = excl, o1 = excl + l0, o2 = excl + l1, o3 = excl + l2;

    // publish per-chunk meta {cnt, local_off}
    int s = 4 * t;
    meta[(s + 0) * ch_stride] = make_int2(tot.x, o0);
    meta[(s + 1) * ch_stride] = make_int2(tot.y, o1);
    meta[(s + 2) * ch_stride] = make_int2(tot.z, o2);
    meta[(s + 3) * ch_stride] = make_int2(tot.w, o3);

    // cursors
    sh[s + 0] = o0; sh[s + 1] = o1; sh[s + 2] = o2; sh[s + 3] = o3;
    __syncthreads();

    // local scatter; batch-relative row id
    int m = chunk * 1024 + 4 * t;
    int q;
    q = atomicAdd(&sh[a.x], 1); rows[q] = m + 0;
    q = atomicAdd(&sh[a.y], 1); rows[q] = m + 1;
    q = atomicAdd(&sh[a.z], 1); rows[q] = m + 2;
    q = atomicAdd(&sh[a.w], 1); rows[q] = m + 3;
}

// ---------------- 2) segsum + write: TWO warps per segment (D halves, float2) -------
__global__ __launch_bounds__(256) void k_segsum_write(const float* __restrict__ src,
                                                      float* __restrict__ out) {
    __shared__ int stage[8][STAGE_CAP];
    int gw   = (blockIdx.x * blockDim.x + threadIdx.x) >> 5;   // 0..BB*SS*2-1
    int lane = threadIdx.x & 31;
    int w    = (threadIdx.x >> 5) & 7;
    if (gw >= BB * SS * 2) return;
    int seg = gw >> 1;          // segment id
    int dh  = gw & 1;           // D-half: floats [dh*64, dh*64+64), float2 per lane
    int b   = seg >> 10;

    // lane-parallel meta load: 16 src ints + 4 tgt ints
    const int* ms_raw = (const int*)(g_meta_s + (size_t)seg * HB);
    const int* mt_raw = (const int*)(g_meta_t + (size_t)seg * HBT);
    int mv = 0;
    if (lane < 16)      mv = ms_raw[lane];
    else if (lane < 20) mv = mt_raw[lane - 16];

    int tc0 = __shfl_sync(0xffffffffu, mv, 16);
    int to0 = __shfl_sync(0xffffffffu, mv, 17);
    int tc1 = __shfl_sync(0xffffffffu, mv, 18);
    int to1 = __shfl_sync(0xffffffffu, mv, 19);
    if (tc0 + tc1 == 0) return;

    int cj[HB], oj[HB], pj[HB];
    int cnt = 0;
    #pragma unroll
    for (int j = 0; j < HB; j++) {
        cj[j] = __shfl_sync(0xffffffffu, mv, 2 * j);
        oj[j] = __shfl_sync(0xffffffffu, mv, 2 * j + 1);
        pj[j] = cnt;
        cnt += cj[j];
    }

    // this warp covers a 256B half of each row: float2 per lane
    const float2* base = (const float2*)(src + (size_t)b * MM * DD + dh * 64) + lane;
    float2 a0 = {0,0}, a1 = {0,0}, a2 = {0,0}, a3 = {0,0};
    const int RS = DD / 2;      // row stride in float2 units

    if (cnt <= STAGE_CAP) {
        if (lane < HB) {
            int c = cj[lane], o = oj[lane], p = pj[lane];
            const int* rp = g_rows_s + b * MM + lane * 1024 + o;
            for (int r = 0; r < c; r++) stage[w][p + r] = rp[r];
        }
        __syncwarp();

        const int* mlist = stage[w];
        int r = 0;
        for (; r + 8 <= cnt; r += 8) {
            float2 v0 = base[(size_t)mlist[r]     * RS];
            float2 v1 = base[(size_t)mlist[r + 1] * RS];
            float2 v2 = base[(size_t)mlist[r + 2] * RS];
            float2 v3 = base[(size_t)mlist[r + 3] * RS];
            float2 v4 = base[(size_t)mlist[r + 4] * RS];
            float2 v5 = base[(size_t)mlist[r + 5] * RS];
            float2 v6 = base[(size_t)mlist[r + 6] * RS];
            float2 v7 = base[(size_t)mlist[r + 7] * RS];
            a0.x += v0.x + v4.x; a0.y += v0.y + v4.y;
            a1.x += v1.x + v5.x; a1.y += v1.y + v5.y;
            a2.x += v2.x + v6.x; a2.y += v2.y + v6.y;
            a3.x += v3.x + v7.x; a3.y += v3.y + v7.y;
        }
        for (; r + 4 <= cnt; r += 4) {
            float2 v0 = base[(size_t)mlist[r]     * RS];
            float2 v1 = base[(size_t)mlist[r + 1] * RS];
            float2 v2 = base[(size_t)mlist[r + 2] * RS];
            float2 v3 = base[(size_t)mlist[r + 3] * RS];
            a0.x += v0.x; a0.y += v0.y;
            a1.x += v1.x; a1.y += v1.y;
            a2.x += v2.x; a2.y += v2.y;
            a3.x += v3.x; a3.y += v3.y;
        }
        for (; r < cnt; r++) {
            float2 v = base[(size_t)mlist[r] * RS];
            a0.x += v.x; a0.y += v.y;
        }
    } else {
        // overflow fallback (practically never taken)
        #pragma unroll
        for (int j = 0; j < HB; j++) {
            const int* rp = g_rows_s + b * MM + j * 1024 + oj[j];
            for (int r = 0; r < cj[j]; r++) {
                float2 v = base[(size_t)rp[r] * RS];
                a0.x += v.x; a0.y += v.y;
            }
        }
    }

    float inv = 1.0f / ((float)cnt + 1e-10f);
    float2 res;
    res.x = (a0.x + a1.x + a2.x + a3.x) * inv;
    res.y = (a0.y + a1.y + a2.y + a3.y) * inv;

    // write this half of every target row
    float2* outb = (float2*)(out + (size_t)b * NN * DD + dh * 64) + lane;
    const int* tp0 = g_rows_t + b * NN + to0;
    for (int r = 0; r < tc0; r++) {
        outb[(size_t)tp0[r] * RS] = res;
    }
    const int* tp1 = g_rows_t + b * NN + 1024 + to1;
    for (int r = 0; r < tc1; r++) {
        outb[(size_t)tp1[r] * RS] = res;
    }
}

// ---------------- launch ----------------
extern "C" void kernel_launch(void* const* d_in, const int* in_sizes, int n_in,
                              void* d_out, int out_size) {
    const int*   idx_tgt = (const int*)d_in[0];
    const int*   idx_src = (const int*)d_in[1];
    const float* src     = (const float*)d_in[2];
    float*       out     = (float*)d_out;

    k_sort        <<<NBLK, 256>>>(idx_src, idx_tgt);
    k_segsum_write<<<(BB * SS * 2 * 32 + 255) / 256, 256>>>(src, out);
}

// round 12
// speedup vs baseline: 1.6871x; 1.3801x over previous
#include <cuda_runtime.h>
#include <cuda_bf16.h>
#include <stdint.h>

#define BB 4
#define NN 2048
#define MM 8192
#define DD 128
#define SS 1024     // NUM_SEGMENTS
#define HB 8        // source chunks per batch, 1024 rows each
#define HBT 2       // target chunks per batch, 1024 rows each
#define NSRC_BLKS (BB * HB)            // 32
#define NTGT_BLKS (BB * HBT)           // 8
#define NBLK (NSRC_BLKS + NTGT_BLKS)   // 40
#define CAP 16                         // per-(chunk,segment) slot capacity
#define SLOT_S (HB * CAP)              // 128 ints per (b,seg) source slot
#define SLOT_T (HBT * CAP)             // 32 ints per (b,seg) target slot

// ---------------- scratch (static __device__, no allocation) ----------------
__device__ int g_rows_s[BB * SS * SLOT_S];   // 2 MB  slotted source rows
__device__ int g_rows_t[BB * SS * SLOT_T];   // 512KB slotted target rows
__device__ int g_cnt_s[BB * HB * SS];        // per-(b,chunk,seg) counts
__device__ int g_cnt_t[BB * HBT * SS];

// ---------------- 1) slotted sort: NO hist, NO scan ----------------
// blocks 0..31: source chunks; 32..39: target chunks
__global__ __launch_bounds__(256) void k_sort(const int* __restrict__ idx_src,
                                              const int* __restrict__ idx_tgt) {
    __shared__ int cur[SS];
    const int t = threadIdx.x;

    const int* in;
    int* rows;        // slot base for this batch
    int* cnt_out;     // counts for this (b,chunk)
    int  slot_shift;  // log2(slot size)
    int  chunk;
    if (blockIdx.x < NSRC_BLKS) {
        int b = blockIdx.x >> 3, j = blockIdx.x & 7;
        in   = idx_src + b * MM + j * 1024;
        rows = g_rows_s + (size_t)b * SS * SLOT_S;
        cnt_out = g_cnt_s + (b * HB + j) * SS;
        slot_shift = 7; chunk = j;
    } else {
        int u = blockIdx.x - NSRC_BLKS;
        int b = u >> 1, j = u & 1;
        in   = idx_tgt + b * NN + j * 1024;
        rows = g_rows_t + (size_t)b * SS * SLOT_T;
        cnt_out = g_cnt_t + (b * HBT + j) * SS;
        slot_shift = 5; chunk = j;
    }

    ((int4*)cur)[t] = make_int4(0, 0, 0, 0);
    __syncthreads();

    const int4 a = ((const int4*)in)[t];
    const int m = chunk * 1024 + 4 * t;     // batch-relative row id
    const int sub = chunk * CAP;
    int q;
    q = atomicAdd(&cur[a.x], 1); if (q < CAP) rows[(a.x << slot_shift) + sub + q] = m + 0;
    q = atomicAdd(&cur[a.y], 1); if (q < CAP) rows[(a.y << slot_shift) + sub + q] = m + 1;
    q = atomicAdd(&cur[a.z], 1); if (q < CAP) rows[(a.z << slot_shift) + sub + q] = m + 2;
    q = atomicAdd(&cur[a.w], 1); if (q < CAP) rows[(a.w << slot_shift) + sub + q] = m + 3;
    __syncthreads();

    ((int4*)cnt_out)[t] = ((int4*)cur)[t];   // final cursors == counts
}

// ---------------- 2) segsum + write: one warp per segment, flat parallel loads ------
__global__ __launch_bounds__(256) void k_segsum_write(const float* __restrict__ src,
                                                      float* __restrict__ out,
                                                      const int* __restrict__ idx_src,
                                                      const int* __restrict__ idx_tgt) {
    __shared__ int raw[8][SLOT_S];       // staged source slot
    __shared__ int trw[8][SLOT_T];       // staged target slot
    __shared__ int cpt[8][SLOT_S];       // compacted source rows
    int seg  = (blockIdx.x * blockDim.x + threadIdx.x) >> 5;   // 0..BB*SS-1
    int lane = threadIdx.x & 31;
    int w    = (threadIdx.x >> 5) & 7;
    if (seg >= BB * SS) return;
    int b    = seg >> 10;
    int sloc = seg & (SS - 1);

    // ---- ALL index loads issued in one parallel wave (no dependent hops) ----
    int c_s = 0, c_t = 0;
    if (lane < HB)  c_s = g_cnt_s[(b * HB  + lane) * SS + sloc];
    if (lane < HBT) c_t = g_cnt_t[(b * HBT + lane) * SS + sloc];
    int4 rv = ((const int4*)(g_rows_s + ((size_t)seg << 7)))[lane];   // 128 ints
    int  tv = (g_rows_t + ((size_t)seg << 5))[lane];                   // 32 ints

    int ct0 = __shfl_sync(0xffffffffu, c_t, 0);
    int ct1 = __shfl_sync(0xffffffffu, c_t, 1);
    int tcnt = ct0 + ct1;
    if (tcnt == 0) return;

    int cj[HB], pj[HB];
    int cnt = 0;
    bool ovf = (ct0 > CAP) | (ct1 > CAP);
    #pragma unroll
    for (int j = 0; j < HB; j++) {
        cj[j] = __shfl_sync(0xffffffffu, c_s, j);
        pj[j] = cnt;
        cnt += cj[j];
        ovf |= (cj[j] > CAP);
    }

    const float* base = src + (size_t)b * MM * DD;
    float4 acc0 = {0,0,0,0}, acc1 = {0,0,0,0}, acc2 = {0,0,0,0}, acc3 = {0,0,0,0};

    if (!ovf) {
        // stage slots to shared, compact chunk sub-lists
        ((int4*)raw[w])[lane] = rv;
        trw[w][lane] = tv;
        __syncwarp();
        if (lane < HB) {
            int c = cj[lane], p = pj[lane];
            const int* s = raw[w] + lane * CAP;
            for (int r = 0; r < c; r++) cpt[w][p + r] = s[r];
        }
        __syncwarp();

        const int* mlist = cpt[w];
        int r = 0;
        for (; r + 8 <= cnt; r += 8) {
            int m0 = mlist[r],   m1 = mlist[r+1], m2 = mlist[r+2], m3 = mlist[r+3];
            int m4 = mlist[r+4], m5 = mlist[r+5], m6 = mlist[r+6], m7 = mlist[r+7];
            float4 v0 = ((const float4*)(base + (size_t)m0 * DD))[lane];
            float4 v1 = ((const float4*)(base + (size_t)m1 * DD))[lane];
            float4 v2 = ((const float4*)(base + (size_t)m2 * DD))[lane];
            float4 v3 = ((const float4*)(base + (size_t)m3 * DD))[lane];
            float4 v4 = ((const float4*)(base + (size_t)m4 * DD))[lane];
            float4 v5 = ((const float4*)(base + (size_t)m5 * DD))[lane];
            float4 v6 = ((const float4*)(base + (size_t)m6 * DD))[lane];
            float4 v7 = ((const float4*)(base + (size_t)m7 * DD))[lane];
            acc0.x += v0.x + v4.x; acc0.y += v0.y + v4.y; acc0.z += v0.z + v4.z; acc0.w += v0.w + v4.w;
            acc1.x += v1.x + v5.x; acc1.y += v1.y + v5.y; acc1.z += v1.z + v5.z; acc1.w += v1.w + v5.w;
            acc2.x += v2.x + v6.x; acc2.y += v2.y + v6.y; acc2.z += v2.z + v6.z; acc2.w += v2.w + v6.w;
            acc3.x += v3.x + v7.x; acc3.y += v3.y + v7.y; acc3.z += v3.z + v7.z; acc3.w += v3.w + v7.w;
        }
        for (; r + 4 <= cnt; r += 4) {
            int m0 = mlist[r], m1 = mlist[r+1], m2 = mlist[r+2], m3 = mlist[r+3];
            float4 v0 = ((const float4*)(base + (size_t)m0 * DD))[lane];
            float4 v1 = ((const float4*)(base + (size_t)m1 * DD))[lane];
            float4 v2 = ((const float4*)(base + (size_t)m2 * DD))[lane];
            float4 v3 = ((const float4*)(base + (size_t)m3 * DD))[lane];
            acc0.x += v0.x; acc0.y += v0.y; acc0.z += v0.z; acc0.w += v0.w;
            acc1.x += v1.x; acc1.y += v1.y; acc1.z += v1.z; acc1.w += v1.w;
            acc2.x += v2.x; acc2.y += v2.y; acc2.z += v2.z; acc2.w += v2.w;
            acc3.x += v3.x; acc3.y += v3.y; acc3.z += v3.z; acc3.w += v3.w;
        }
        for (; r < cnt; r++) {
            int m = mlist[r];
            float4 v = ((const float4*)(base + (size_t)m * DD))[lane];
            acc0.x += v.x; acc0.y += v.y; acc0.z += v.z; acc0.w += v.w;
        }
    } else {
        // overflow fallback (P ~ 1e-10): ballot-scan the raw source indices
        const int* is = idx_src + b * MM;
        for (int i0 = 0; i0 < MM; i0 += 32) {
            int id = is[i0 + lane];
            unsigned mask = __ballot_sync(0xffffffffu, id == sloc);
            while (mask) {
                int bit = __ffs(mask) - 1;
                mask &= mask - 1;
                float4 v = ((const float4*)(base + (size_t)(i0 + bit) * DD))[lane];
                acc0.x += v.x; acc0.y += v.y; acc0.z += v.z; acc0.w += v.w;
            }
        }
    }

    float inv = 1.0f / ((float)cnt + 1e-10f);
    float4 res;
    res.x = (acc0.x + acc1.x + acc2.x + acc3.x) * inv;
    res.y = (acc0.y + acc1.y + acc2.y + acc3.y) * inv;
    res.z = (acc0.z + acc1.z + acc2.z + acc3.z) * inv;
    res.w = (acc0.w + acc1.w + acc2.w + acc3.w) * inv;

    float* outb = out + (size_t)b * NN * DD;
    if (!ovf) {
        for (int r = 0; r < ct0; r++) {
            int n = trw[w][r];
            ((float4*)(outb + (size_t)n * DD))[lane] = res;
        }
        for (int r = 0; r < ct1; r++) {
            int n = trw[w][CAP + r];
            ((float4*)(outb + (size_t)n * DD))[lane] = res;
        }
    } else {
        // target fallback: scan raw target indices
        const int* it = idx_tgt + b * NN;
        for (int i0 = 0; i0 < NN; i0 += 32) {
            int id = it[i0 + lane];
            unsigned mask = __ballot_sync(0xffffffffu, id == sloc);
            while (mask) {
                int bit = __ffs(mask) - 1;
                mask &= mask - 1;
                ((float4*)(outb + (size_t)(i0 + bit) * DD))[lane] = res;
            }
        }
    }
}

// ---------------- launch ----------------
extern "C" void kernel_launch(void* const* d_in, const int* in_sizes, int n_in,
                              void* d_out, int out_size) {
    const int*   idx_tgt = (const int*)d_in[0];
    const int*   idx_src = (const int*)d_in[1];
    const float* src     = (const float*)d_in[2];
    float*       out     = (float*)d_out;

    k_sort        <<<NBLK, 256>>>(idx_src, idx_tgt);
    k_segsum_write<<<(BB * SS * 32 + 255) / 256, 256>>>(src, out, idx_src, idx_tgt);
}